// round 1
// baseline (speedup 1.0000x reference)
#include <cuda_runtime.h>
#include <cuda_bf16.h>
#include <cstddef>

// Problem constants
#define BB    16
#define SS    4096
#define DD    1024      // D_IN
#define HH    1024
#define DOUT  1024
#define SPLIT 128
#define ROWS  (SS / SPLIT)   // 32 rows per pass1 block

// Scratch: __device__ globals (no cudaMalloc allowed)
__device__ float g_partial[BB * SPLIT * DD];   // [B][SPLIT][D], 8 MB
__device__ float g_m[BB * DD];                 // mean, 64 KB
__device__ float g_enc[BB * HH];               // hidden, 64 KB

// ---------------------------------------------------------------------------
// Pass 1: partial sums over S. grid = (SPLIT, B), block = 256 threads.
// Each block streams ROWS=32 rows of D=1024 floats with float4 loads.
// ---------------------------------------------------------------------------
__global__ __launch_bounds__(256) void pass1_kernel(const float* __restrict__ x) {
    const int split = blockIdx.x;
    const int b     = blockIdx.y;
    const int t     = threadIdx.x;           // 0..255; t*4 covers D=1024

    const float4* xp = reinterpret_cast<const float4*>(
        x + ((size_t)b * SS + (size_t)split * ROWS) * DD);

    float4 acc = make_float4(0.f, 0.f, 0.f, 0.f);
    #pragma unroll 8
    for (int r = 0; r < ROWS; ++r) {
        float4 v = xp[(size_t)r * (DD / 4) + t];
        acc.x += v.x; acc.y += v.y; acc.z += v.z; acc.w += v.w;
    }

    float4* out = reinterpret_cast<float4*>(
        g_partial + ((size_t)b * SPLIT + split) * DD);
    out[t] = acc;
}

// ---------------------------------------------------------------------------
// Pass 2: reduce SPLIT partials -> mean. grid = B*D/256 = 64 blocks.
// Reads are coalesced across d (stride-D within the split loop).
// ---------------------------------------------------------------------------
__global__ __launch_bounds__(256) void pass2_kernel() {
    const int idx = blockIdx.x * 256 + threadIdx.x;   // over B*D = 16384
    const int b = idx / DD;
    const int d = idx % DD;

    const float* p = g_partial + (size_t)b * SPLIT * DD + d;
    float s = 0.f;
    #pragma unroll 8
    for (int i = 0; i < SPLIT; ++i) s += p[(size_t)i * DD];

    g_m[idx] = s * (1.0f / (float)SS);
}

// ---------------------------------------------------------------------------
// GEMV x16:  y[b][n] = sum_k v[b][k] * W[n][k] + bias[n]
// B=16, K=1024, N=1024.
// Block = 256 threads (8 warps), each warp computes 2 output rows n,
// 16 rows n per block, grid = 64 blocks.
// Full activation matrix v (16x1024 fp32 = 64 KB) cached in dynamic smem.
// Inner loop: 1 m-float4 load feeds 2 (n) x 4 FMAs x 16 (b) accumulators.
// ---------------------------------------------------------------------------
__global__ __launch_bounds__(256) void gemv16_kernel(
    const float* __restrict__ v,
    const float* __restrict__ W,
    const float* __restrict__ bias,
    float* __restrict__ y)
{
    extern __shared__ float sv[];   // 16*1024 floats = 64 KB

    const int t = threadIdx.x;
    // Cooperative load of v into shared (float4): 4096 float4 / 256 thr = 16 iters
    {
        const float4* vsrc = reinterpret_cast<const float4*>(v);
        float4*       vdst = reinterpret_cast<float4*>(sv);
        #pragma unroll
        for (int i = 0; i < (BB * DD / 4) / 256; ++i)
            vdst[i * 256 + t] = vsrc[i * 256 + t];
    }
    __syncthreads();

    const int warp = t >> 5;
    const int lane = t & 31;
    const int n0 = blockIdx.x * 16 + warp * 2;   // 2 rows per warp

    float acc0[BB], acc1[BB];
    #pragma unroll
    for (int b = 0; b < BB; ++b) { acc0[b] = 0.f; acc1[b] = 0.f; }

    const float4* W0 = reinterpret_cast<const float4*>(W + (size_t)(n0    ) * DD);
    const float4* W1 = reinterpret_cast<const float4*>(W + (size_t)(n0 + 1) * DD);

    // K=1024: each lane covers 4 floats, 32 lanes -> 128 floats/iter, 8 iters
    #pragma unroll
    for (int i = 0; i < 8; ++i) {
        const int kk = i * 32 + lane;           // float4 index in row
        float4 w0 = W0[kk];
        float4 w1 = W1[kk];
        #pragma unroll
        for (int b = 0; b < BB; ++b) {
            float4 m4 = reinterpret_cast<const float4*>(sv + b * DD)[kk];
            acc0[b] += m4.x * w0.x + m4.y * w0.y + m4.z * w0.z + m4.w * w0.w;
            acc1[b] += m4.x * w1.x + m4.y * w1.y + m4.z * w1.z + m4.w * w1.w;
        }
    }

    // Warp-reduce each accumulator; lane 0 writes.
    const float bias0 = bias[n0];
    const float bias1 = bias[n0 + 1];
    #pragma unroll
    for (int b = 0; b < BB; ++b) {
        float a0 = acc0[b];
        float a1 = acc1[b];
        #pragma unroll
        for (int off = 16; off > 0; off >>= 1) {
            a0 += __shfl_xor_sync(0xffffffffu, a0, off);
            a1 += __shfl_xor_sync(0xffffffffu, a1, off);
        }
        if (lane == 0) {
            y[(size_t)b * DOUT + n0]     = a0 + bias0;
            y[(size_t)b * DOUT + n0 + 1] = a1 + bias1;
        }
    }
}

// ---------------------------------------------------------------------------
// Launch. Inputs (metadata order): x, W_enc, b_enc, W_out, b_out.
// Output: [B, D_OUT] fp32.
// ---------------------------------------------------------------------------
extern "C" void kernel_launch(void* const* d_in, const int* in_sizes, int n_in,
                              void* d_out, int out_size)
{
    const float* x     = (const float*)d_in[0];
    const float* W_enc = (const float*)d_in[1];
    const float* b_enc = (const float*)d_in[2];
    const float* W_out = (const float*)d_in[3];
    const float* b_out = (const float*)d_in[4];
    float*       out   = (float*)d_out;

    // Resolve device-global scratch addresses (host API, not a stream op —
    // safe under graph capture; no allocation performed).
    static float* p_m   = nullptr;
    static float* p_enc = nullptr;
    if (!p_m)   cudaGetSymbolAddress((void**)&p_m,   g_m);
    if (!p_enc) cudaGetSymbolAddress((void**)&p_enc, g_enc);

    // 64 KB dynamic smem for the GEMV kernel (above the 48 KB default).
    static bool attr_set = false;
    if (!attr_set) {
        cudaFuncSetAttribute(gemv16_kernel,
                             cudaFuncAttributeMaxDynamicSharedMemorySize,
                             BB * DD * (int)sizeof(float));
        attr_set = true;
    }

    // 1) partial sums over S
    pass1_kernel<<<dim3(SPLIT, BB), 256>>>(x);
    // 2) final mean
    pass2_kernel<<<(BB * DD) / 256, 256>>>();
    // 3) enc = m @ W_enc^T + b_enc
    gemv16_kernel<<<HH / 16, 256, BB * DD * sizeof(float)>>>(p_m, W_enc, b_enc, p_enc);
    // 4) out = enc @ W_out^T + b_out
    gemv16_kernel<<<DOUT / 16, 256, BB * DD * sizeof(float)>>>(p_enc, W_out, b_out, out);
}

// round 3
// speedup vs baseline: 1.1200x; 1.1200x over previous
#include <cuda_runtime.h>
#include <cuda_bf16.h>
#include <cstddef>

// Problem constants
#define BB    16
#define SS    4096
#define DD    1024      // D_IN
#define HH    1024
#define DOUT  1024
#define SPLIT 128
#define ROWS  (SS / SPLIT)   // 32 rows per pass1 block

// GEMV tiling
#define KSPLIT  4
#define KCHUNK  (DD / KSPLIT)      // 256 floats per K-chunk
#define KC4     (KCHUNK / 4)       // 64 float4 per row-chunk
#define NPW     4                  // n-rows per warp
#define NPB     (8 * NPW)          // 32 n-rows per block
#define NGROUPS (HH / NPB)         // 32 n-groups

// Scratch: __device__ globals (no cudaMalloc allowed)
__device__ float g_partial[BB * SPLIT * DD];        // pass1 partials, 8 MB
__device__ float g_m[BB * DD];                      // mean, 64 KB
__device__ float g_pA[KSPLIT * BB * HH];            // gemvA partials, 256 KB
__device__ float g_pB[KSPLIT * BB * DOUT];          // gemvB partials, 256 KB

// ---------------------------------------------------------------------------
// Pass 1: partial sums over S. grid = (SPLIT, B), block = 256 threads.
// ---------------------------------------------------------------------------
__global__ __launch_bounds__(256) void pass1_kernel(const float* __restrict__ x) {
    const int split = blockIdx.x;
    const int b     = blockIdx.y;
    const int t     = threadIdx.x;

    const float4* xp = reinterpret_cast<const float4*>(
        x + ((size_t)b * SS + (size_t)split * ROWS) * DD);

    float4 acc = make_float4(0.f, 0.f, 0.f, 0.f);
    #pragma unroll 8
    for (int r = 0; r < ROWS; ++r) {
        float4 v = xp[(size_t)r * (DD / 4) + t];
        acc.x += v.x; acc.y += v.y; acc.z += v.z; acc.w += v.w;
    }

    float4* out = reinterpret_cast<float4*>(
        g_partial + ((size_t)b * SPLIT + split) * DD);
    out[t] = acc;
}

// ---------------------------------------------------------------------------
// Pass 2: reduce SPLIT partials -> mean. 64 blocks x 256 threads.
// ---------------------------------------------------------------------------
__global__ __launch_bounds__(256) void pass2_kernel() {
    const int idx = blockIdx.x * 256 + threadIdx.x;   // over B*D = 16384
    const int b = idx / DD;
    const int d = idx % DD;

    const float* p = g_partial + (size_t)b * SPLIT * DD + d;
    float s = 0.f;
    #pragma unroll 8
    for (int i = 0; i < SPLIT; ++i) s += p[(size_t)i * DD];

    g_m[idx] = s * (1.0f / (float)SS);
}

// ---------------------------------------------------------------------------
// K-split GEMV partial:  pout[ks][b][n] = sum_{k in chunk ks} v[b][k]*W[n][k]
// grid = (NGROUPS, KSPLIT) = (32, 4) = 128 blocks, block = 256 (8 warps).
// Warp w computes NPW=4 n-rows for all 16 b. smem holds the 16xKCHUNK v tile.
// If FUSE4: v[b][k] = sum_{j<4} vsrc[j][b][k] + vbias[k]  (fuses the previous
// GEMV's K-split reduction + bias into this kernel's smem fill).
// ---------------------------------------------------------------------------
template <bool FUSE4>
__global__ __launch_bounds__(256) void gemv_part_kernel(
    const float* __restrict__ vsrc,
    const float* __restrict__ vbias,
    const float* __restrict__ W,
    float* __restrict__ pout)
{
    __shared__ float4 sv4[BB * KC4];   // 16 x 64 float4 = 16 KB

    const int t  = threadIdx.x;
    const int ng = blockIdx.x;
    const int ks = blockIdx.y;

    // ---- fill smem v tile ------------------------------------------------
    {
        const float4* V4 = reinterpret_cast<const float4*>(vsrc);
        const float4* B4 = FUSE4 ? reinterpret_cast<const float4*>(vbias) : nullptr;
        #pragma unroll
        for (int i = 0; i < (BB * KC4) / 256; ++i) {      // 4 iterations
            const int fid = i * 256 + t;                  // 0..1023
            const int b   = fid >> 6;                     // /64
            const int kk  = fid & 63;
            const int g   = b * (DD / 4) + ks * KC4 + kk; // float4 index in [B,D]
            float4 v;
            if (FUSE4) {
                float4 a0 = V4[g];
                float4 a1 = V4[g + BB * DD / 4];
                float4 a2 = V4[g + 2 * BB * DD / 4];
                float4 a3 = V4[g + 3 * BB * DD / 4];
                float4 bb = B4[ks * KC4 + kk];
                v.x = a0.x + a1.x + a2.x + a3.x + bb.x;
                v.y = a0.y + a1.y + a2.y + a3.y + bb.y;
                v.z = a0.z + a1.z + a2.z + a3.z + bb.z;
                v.w = a0.w + a1.w + a2.w + a3.w + bb.w;
            } else {
                v = V4[g];
            }
            sv4[fid] = v;
        }
    }
    __syncthreads();

    // ---- main compute ----------------------------------------------------
    const int warp = t >> 5;
    const int lane = t & 31;
    const int n0   = ng * NPB + warp * NPW;

    float acc[NPW][BB];
    #pragma unroll
    for (int j = 0; j < NPW; ++j)
        #pragma unroll
        for (int b = 0; b < BB; ++b) acc[j][b] = 0.f;

    const float4* W4 = reinterpret_cast<const float4*>(W);

    #pragma unroll
    for (int i = 0; i < KC4 / 32; ++i) {                  // 2 iterations
        const int kk = i * 32 + lane;                     // float4 idx in chunk
        float4 w4[NPW];
        #pragma unroll
        for (int j = 0; j < NPW; ++j)
            w4[j] = W4[(size_t)(n0 + j) * (DD / 4) + ks * KC4 + kk];

        #pragma unroll
        for (int b = 0; b < BB; ++b) {
            float4 m4 = sv4[b * KC4 + kk];
            #pragma unroll
            for (int j = 0; j < NPW; ++j) {
                acc[j][b] += m4.x * w4[j].x + m4.y * w4[j].y
                           + m4.z * w4[j].z + m4.w * w4[j].w;
            }
        }
    }

    // ---- warp reduce + write --------------------------------------------
    #pragma unroll
    for (int j = 0; j < NPW; ++j) {
        #pragma unroll
        for (int b = 0; b < BB; ++b) {
            float a = acc[j][b];
            #pragma unroll
            for (int off = 16; off > 0; off >>= 1)
                a += __shfl_xor_sync(0xffffffffu, a, off);
            if (lane == 0)
                pout[(size_t)ks * BB * HH + (size_t)b * HH + n0 + j] = a;
        }
    }
}

// ---------------------------------------------------------------------------
// Final reduce: out[b][n] = sum_ks pB[ks][b][n] + b_out[n]. 64 x 256.
// ---------------------------------------------------------------------------
__global__ __launch_bounds__(256) void reduce_out_kernel(
    const float* __restrict__ bias, float* __restrict__ out)
{
    const int idx = blockIdx.x * 256 + threadIdx.x;   // over B*DOUT = 16384
    const int n = idx & (DOUT - 1);
    float s = g_pB[idx] + g_pB[idx + BB * DOUT] + g_pB[idx + 2 * BB * DOUT]
            + g_pB[idx + 3 * BB * DOUT] + bias[n];
    out[idx] = s;
}

// ---------------------------------------------------------------------------
// Launch. Inputs (metadata order): x, W_enc, b_enc, W_out, b_out.
// ---------------------------------------------------------------------------
extern "C" void kernel_launch(void* const* d_in, const int* in_sizes, int n_in,
                              void* d_out, int out_size)
{
    const float* x     = (const float*)d_in[0];
    const float* W_enc = (const float*)d_in[1];
    const float* b_enc = (const float*)d_in[2];
    const float* W_out = (const float*)d_in[3];
    const float* b_out = (const float*)d_in[4];
    float*       out   = (float*)d_out;

    static float* p_m  = nullptr;
    static float* p_pA = nullptr;
    static float* p_pB = nullptr;
    if (!p_m)  cudaGetSymbolAddress((void**)&p_m,  g_m);
    if (!p_pA) cudaGetSymbolAddress((void**)&p_pA, g_pA);
    if (!p_pB) cudaGetSymbolAddress((void**)&p_pB, g_pB);

    // 1) partial sums over S
    pass1_kernel<<<dim3(SPLIT, BB), 256>>>(x);
    // 2) final mean
    pass2_kernel<<<(BB * DD) / 256, 256>>>();
    // 3) enc partials = m @ W_enc^T (K-split)
    gemv_part_kernel<false><<<dim3(NGROUPS, KSPLIT), 256>>>(p_m, nullptr, W_enc, p_pA);
    // 4) out partials = (reduce(encparts)+b_enc) @ W_out^T (K-split, fused fill)
    gemv_part_kernel<true><<<dim3(NGROUPS, KSPLIT), 256>>>(p_pA, b_enc, W_out, p_pB);
    // 5) final reduce + b_out
    reduce_out_kernel<<<(BB * DOUT) / 256, 256>>>(b_out, out);
}

// round 4
// speedup vs baseline: 1.2833x; 1.1458x over previous
#include <cuda_runtime.h>
#include <cuda_bf16.h>
#include <cstddef>

// Problem constants
#define BB    16
#define SS    4096
#define DD    1024      // D_IN
#define HH    1024
#define DOUT  1024
#define SPLIT 128
#define ROWS  (SS / SPLIT)   // 32 rows per pass1 block

// GEMV tiling: one output per thread
#define KS2   16                  // K splits
#define KC4B  ((DD / KS2) / 4)    // 16 float4 per row-chunk
#define NT    16                  // n-tile per block
#define PAD   17                  // float4 row stride in smem (16 + 1 pad)

// Scratch: __device__ globals (no cudaMalloc allowed)
__device__ float g_partial[BB * SPLIT * DD];   // pass1 partials, 8 MB
__device__ float g_m4[4 * BB * DD];            // pass2a partials, 256 KB
__device__ float g_m[BB * DD];                 // mean, 64 KB
__device__ float g_enc[BB * HH];               // hidden, 64 KB
__device__ float g_pA[KS2 * BB * HH];          // gemvA partials, 1 MB
__device__ float g_pB[KS2 * BB * DOUT];        // gemvB partials, 1 MB

// ---------------------------------------------------------------------------
// Pass 1: partial sums over S. grid = (SPLIT, B), block = 256 threads.
// Streaming loads (no reuse of x) with 16-deep unroll for MLP.
// ---------------------------------------------------------------------------
__global__ __launch_bounds__(256) void pass1_kernel(const float* __restrict__ x) {
    const int split = blockIdx.x;
    const int b     = blockIdx.y;
    const int t     = threadIdx.x;

    const float4* xp = reinterpret_cast<const float4*>(
        x + ((size_t)b * SS + (size_t)split * ROWS) * DD);

    float4 acc = make_float4(0.f, 0.f, 0.f, 0.f);
    #pragma unroll 16
    for (int r = 0; r < ROWS; ++r) {
        float4 v = __ldcs(&xp[(size_t)r * (DD / 4) + t]);
        acc.x += v.x; acc.y += v.y; acc.z += v.z; acc.w += v.w;
    }

    float4* out = reinterpret_cast<float4*>(
        g_partial + ((size_t)b * SPLIT + split) * DD);
    out[t] = acc;
}

// ---------------------------------------------------------------------------
// Pass 2a: reduce 128 partials in 4 groups of 32. grid = (64, 4), 256 thr.
// ---------------------------------------------------------------------------
__global__ __launch_bounds__(256) void pass2a_kernel() {
    const int idx = blockIdx.x * 256 + threadIdx.x;   // over B*D = 16384
    const int kp  = blockIdx.y;                        // 0..3
    const int b = idx / DD;
    const int d = idx % DD;

    const float* p = g_partial + (size_t)b * SPLIT * DD + (size_t)kp * 32 * DD + d;
    float s = 0.f;
    #pragma unroll 8
    for (int i = 0; i < 32; ++i) s += p[(size_t)i * DD];

    g_m4[(size_t)kp * (BB * DD) + idx] = s;
}

// ---------------------------------------------------------------------------
// Pass 2b: final 4-way reduce + scale. 64 blocks x 256 threads.
// ---------------------------------------------------------------------------
__global__ __launch_bounds__(256) void pass2b_kernel() {
    const int idx = blockIdx.x * 256 + threadIdx.x;
    float s = g_m4[idx] + g_m4[idx + BB * DD] + g_m4[idx + 2 * BB * DD]
            + g_m4[idx + 3 * BB * DD];
    g_m[idx] = s * (1.0f / (float)SS);
}

// ---------------------------------------------------------------------------
// K-split GEMV, one output per thread:
//   pout[ks][b][n] = sum_{k in chunk ks} v[b][k] * W[n][k]
// grid = (N/NT, KS2) = (64, 16) = 1024 blocks, block = 256 threads.
// Thread t computes output (n = n0 + (t&15), b = t>>4). No warp reduce.
// smem: v-tile [16][16 f4] and W-tile [16][16 f4], padded rows.
// ---------------------------------------------------------------------------
__global__ __launch_bounds__(256) void gemv_ks_kernel(
    const float* __restrict__ v,
    const float* __restrict__ W,
    float* __restrict__ pout)
{
    __shared__ float4 sV[BB * PAD];
    __shared__ float4 sW[NT * PAD];

    const int t  = threadIdx.x;
    const int n0 = blockIdx.x * NT;
    const int ks = blockIdx.y;

    // Fill: 256 threads load exactly 256 float4 per tile, coalesced
    // (thread -> (row = t>>4, k4 = t&15); 16 consecutive float4 per row).
    {
        const int row = t >> 4;
        const int k4  = t & 15;
        sV[row * PAD + k4] = reinterpret_cast<const float4*>(v)
            [(size_t)row * (DD / 4) + ks * KC4B + k4];
        sW[row * PAD + k4] = reinterpret_cast<const float4*>(W)
            [(size_t)(n0 + row) * (DD / 4) + ks * KC4B + k4];
    }
    __syncthreads();

    const int nl = t & 15;
    const int b  = t >> 4;

    float acc = 0.f;
    #pragma unroll
    for (int k4 = 0; k4 < KC4B; ++k4) {
        float4 m4 = sV[b  * PAD + k4];   // 16 lanes share (broadcast x2 per warp)
        float4 w4 = sW[nl * PAD + k4];   // per-lane distinct rows
        acc += m4.x * w4.x + m4.y * w4.y + m4.z * w4.z + m4.w * w4.w;
    }

    pout[(size_t)ks * (BB * HH) + (size_t)b * HH + n0 + nl] = acc;
}

// ---------------------------------------------------------------------------
// Reduce KS2 partials + bias. 64 blocks x 256 threads. out[b][n].
// ---------------------------------------------------------------------------
__global__ __launch_bounds__(256) void reduce16_kernel(
    const float* __restrict__ pin,
    const float* __restrict__ bias,
    float* __restrict__ out)
{
    const int idx = blockIdx.x * 256 + threadIdx.x;   // over B*N = 16384
    const int n = idx & (HH - 1);
    float s = bias[n];
    #pragma unroll
    for (int i = 0; i < KS2; ++i) s += pin[(size_t)i * (BB * HH) + idx];
    out[idx] = s;
}

// ---------------------------------------------------------------------------
// Launch. Inputs (metadata order): x, W_enc, b_enc, W_out, b_out.
// ---------------------------------------------------------------------------
extern "C" void kernel_launch(void* const* d_in, const int* in_sizes, int n_in,
                              void* d_out, int out_size)
{
    const float* x     = (const float*)d_in[0];
    const float* W_enc = (const float*)d_in[1];
    const float* b_enc = (const float*)d_in[2];
    const float* W_out = (const float*)d_in[3];
    const float* b_out = (const float*)d_in[4];
    float*       out   = (float*)d_out;

    static float* p_m   = nullptr;
    static float* p_enc = nullptr;
    static float* p_pA  = nullptr;
    static float* p_pB  = nullptr;
    if (!p_m)   cudaGetSymbolAddress((void**)&p_m,   g_m);
    if (!p_enc) cudaGetSymbolAddress((void**)&p_enc, g_enc);
    if (!p_pA)  cudaGetSymbolAddress((void**)&p_pA,  g_pA);
    if (!p_pB)  cudaGetSymbolAddress((void**)&p_pB,  g_pB);

    // 1) partial sums over S
    pass1_kernel<<<dim3(SPLIT, BB), 256>>>(x);
    // 2) mean, two levels
    pass2a_kernel<<<dim3(64, 4), 256>>>();
    pass2b_kernel<<<64, 256>>>();
    // 3) enc = m @ W_enc^T + b_enc (K-split partials, then reduce)
    gemv_ks_kernel<<<dim3(HH / NT, KS2), 256>>>(p_m, W_enc, p_pA);
    reduce16_kernel<<<64, 256>>>(p_pA, b_enc, p_enc);
    // 4) out = enc @ W_out^T + b_out
    gemv_ks_kernel<<<dim3(DOUT / NT, KS2), 256>>>(p_enc, W_out, p_pB);
    reduce16_kernel<<<64, 256>>>(p_pB, b_out, out);
}

// round 5
// speedup vs baseline: 1.4128x; 1.1009x over previous
#include <cuda_runtime.h>
#include <cuda_bf16.h>
#include <cstddef>

// Problem constants
#define BB    16
#define SS    4096
#define DD    1024      // D_IN
#define HH    1024
#define DOUT  1024
#define SPLIT 64
#define ROWS  (SS / SPLIT)   // 64 rows per pass1 block

// GEMV tiling
#define KS    16                  // k-chunks (blockIdx.y)
#define SUBK  2                   // sub-splits within a block
#define KS2   (KS * SUBK)         // 32 total K-splits in partial buffers
#define CF4   ((DD / KS) / 4)     // 16 float4 per block chunk
#define PF4   (CF4 / SUBK)        // 8 float4 per thread
#define NT    128                 // n-rows per block

// Scratch: __device__ globals (no cudaMalloc allowed)
__device__ float g_partial[BB * SPLIT * DD];   // pass1 partials, 4 MB
__device__ float g_m4[4 * BB * DD];            // pass2a partials, 256 KB
__device__ float g_pA[KS2 * BB * HH];          // gemvA partials, 2 MB
__device__ float g_pB[KS2 * BB * DOUT];        // gemvB partials, 2 MB

// ---------------------------------------------------------------------------
// Pass 1: partial sums over S. grid = (SPLIT, B) = (64,16), block = 256.
// Each block streams 64 rows of D=1024 with streaming float4 loads.
// ---------------------------------------------------------------------------
__global__ __launch_bounds__(256) void pass1_kernel(const float* __restrict__ x) {
    const int split = blockIdx.x;
    const int b     = blockIdx.y;
    const int t     = threadIdx.x;

    const float4* xp = reinterpret_cast<const float4*>(
        x + ((size_t)b * SS + (size_t)split * ROWS) * DD);

    float4 acc = make_float4(0.f, 0.f, 0.f, 0.f);
    #pragma unroll 16
    for (int r = 0; r < ROWS; ++r) {
        float4 v = __ldcs(&xp[(size_t)r * (DD / 4) + t]);
        acc.x += v.x; acc.y += v.y; acc.z += v.z; acc.w += v.w;
    }

    float4* out = reinterpret_cast<float4*>(
        g_partial + ((size_t)b * SPLIT + split) * DD);
    out[t] = acc;
}

// ---------------------------------------------------------------------------
// Pass 2a: reduce 64 partials in 4 groups of 16 -> g_m4. grid (64,4) x 256.
// ---------------------------------------------------------------------------
__global__ __launch_bounds__(256) void pass2a_kernel() {
    const int idx = blockIdx.x * 256 + threadIdx.x;   // over B*D = 16384
    const int kp  = blockIdx.y;                        // 0..3
    const int b = idx / DD;
    const int d = idx % DD;

    const float* p = g_partial + (size_t)b * SPLIT * DD + (size_t)kp * 16 * DD + d;
    float s = 0.f;
    #pragma unroll
    for (int i = 0; i < 16; ++i) s += p[(size_t)i * DD];

    g_m4[(size_t)kp * (BB * DD) + idx] = s;
}

// ---------------------------------------------------------------------------
// GEMV partial, W-in-registers / v-broadcast-from-smem.
//   pout[ks2][b][n] = sum_{k in sub-chunk} v[b][k] * W[n][k]
// grid = (N/NT, KS) = (8, 16) = 128 blocks, block = 256 threads.
// Thread: n = n0 + (t & 127), sub = t >> 7. acc[16] over all b. No warp reduce.
// MODE 0: v = (sum of 4 g_m4 slices) * 1/SS            (mean finalize fused)
// MODE 1: v = (sum of 32 g_pA slices) + bias           (prev reduce fused)
// ---------------------------------------------------------------------------
template <int MODE>
__global__ __launch_bounds__(256) void gemv_kernel(
    const float* __restrict__ vsrc,
    const float* __restrict__ bias,
    const float* __restrict__ W,
    float* __restrict__ pout)
{
    __shared__ float4 sV[BB * CF4];   // 16 b x 16 f4 = 4 KB (block's 64-k chunk)

    const int t  = threadIdx.x;
    const int n0 = blockIdx.x * NT;
    const int ks = blockIdx.y;

    // ---- fill v tile: thread t -> (b = t>>4, k4 = t&15), one float4 each ----
    {
        const int b  = t >> 4;
        const int k4 = t & 15;
        const size_t g = (size_t)b * (DD / 4) + (size_t)ks * CF4 + k4;
        const float4* V4 = reinterpret_cast<const float4*>(vsrc);
        float4 v;
        if (MODE == 0) {
            float4 a0 = V4[g];
            float4 a1 = V4[g + (BB * DD) / 4];
            float4 a2 = V4[g + 2 * (BB * DD) / 4];
            float4 a3 = V4[g + 3 * (BB * DD) / 4];
            const float inv = 1.0f / (float)SS;
            v.x = (a0.x + a1.x + a2.x + a3.x) * inv;
            v.y = (a0.y + a1.y + a2.y + a3.y) * inv;
            v.z = (a0.z + a1.z + a2.z + a3.z) * inv;
            v.w = (a0.w + a1.w + a2.w + a3.w) * inv;
        } else {
            float4 bb = reinterpret_cast<const float4*>(bias)[ks * CF4 + k4];
            v = bb;
            #pragma unroll
            for (int j = 0; j < KS2; ++j) {
                float4 a = V4[g + (size_t)j * ((BB * HH) / 4)];
                v.x += a.x; v.y += a.y; v.z += a.z; v.w += a.w;
            }
        }
        sV[t] = v;
    }
    __syncthreads();

    // ---- compute ---------------------------------------------------------
    const int n   = n0 + (t & (NT - 1));
    const int sub = t >> 7;                    // 0 or 1 (warp-uniform)

    // Load this thread's W slice into registers (8 independent LDG.128)
    const float4* Wr = reinterpret_cast<const float4*>(W)
        + (size_t)n * (DD / 4) + (size_t)ks * CF4 + sub * PF4;
    float4 w[PF4];
    #pragma unroll
    for (int i = 0; i < PF4; ++i) w[i] = Wr[i];

    float acc[BB];
    #pragma unroll
    for (int b = 0; b < BB; ++b) acc[b] = 0.f;

    #pragma unroll
    for (int i = 0; i < PF4; ++i) {
        #pragma unroll
        for (int b = 0; b < BB; ++b) {
            // broadcast: all lanes in the warp read the same address
            float4 m4 = sV[b * CF4 + sub * PF4 + i];
            acc[b] += m4.x * w[i].x + m4.y * w[i].y
                    + m4.z * w[i].z + m4.w * w[i].w;
        }
    }

    // ---- write partials: coalesced across lanes (consecutive n) ----------
    const size_t base = (size_t)(ks * SUBK + sub) * (BB * HH) + n;
    #pragma unroll
    for (int b = 0; b < BB; ++b)
        pout[base + (size_t)b * HH] = acc[b];
}

// ---------------------------------------------------------------------------
// Final reduce: out[b][n] = sum_{32 splits} g_pB + b_out[n]. 64 x 256.
// ---------------------------------------------------------------------------
__global__ __launch_bounds__(256) void reduce_out_kernel(
    const float* __restrict__ bias, float* __restrict__ out)
{
    const int idx = blockIdx.x * 256 + threadIdx.x;   // over B*DOUT = 16384
    const int n = idx & (DOUT - 1);
    float s = bias[n];
    #pragma unroll
    for (int j = 0; j < KS2; ++j) s += g_pB[(size_t)j * (BB * DOUT) + idx];
    out[idx] = s;
}

// ---------------------------------------------------------------------------
// Launch. Inputs (metadata order): x, W_enc, b_enc, W_out, b_out.
// ---------------------------------------------------------------------------
extern "C" void kernel_launch(void* const* d_in, const int* in_sizes, int n_in,
                              void* d_out, int out_size)
{
    const float* x     = (const float*)d_in[0];
    const float* W_enc = (const float*)d_in[1];
    const float* b_enc = (const float*)d_in[2];
    const float* W_out = (const float*)d_in[3];
    const float* b_out = (const float*)d_in[4];
    float*       out   = (float*)d_out;

    static float* p_m4 = nullptr;
    static float* p_pA = nullptr;
    static float* p_pB = nullptr;
    if (!p_m4) cudaGetSymbolAddress((void**)&p_m4, g_m4);
    if (!p_pA) cudaGetSymbolAddress((void**)&p_pA, g_pA);
    if (!p_pB) cudaGetSymbolAddress((void**)&p_pB, g_pB);

    // 1) partial sums over S
    pass1_kernel<<<dim3(SPLIT, BB), 256>>>(x);
    // 2) reduce 64 -> 4 partials
    pass2a_kernel<<<dim3(64, 4), 256>>>();
    // 3) enc partials = mean(x) @ W_enc^T  (mean finalize fused into fill)
    gemv_kernel<0><<<dim3(HH / NT, KS), 256>>>(p_m4, nullptr, W_enc, p_pA);
    // 4) out partials = (enc + b_enc) @ W_out^T  (32-way reduce fused into fill)
    gemv_kernel<1><<<dim3(DOUT / NT, KS), 256>>>(p_pA, b_enc, W_out, p_pB);
    // 5) final reduce + b_out
    reduce_out_kernel<<<64, 256>>>(b_out, out);
}